// round 1
// baseline (speedup 1.0000x reference)
#include <cuda_runtime.h>
#include <math.h>

// Problem constants
#define FRAME_SIZE 160
#define LPC_N 16
#define T_LEN 2400          // 160 * 15
#define N_FRAMES 15
#define B_SZ 1024

#define SCALE    (255.0f / 32768.0f)
#define SCALE_1  (32768.0f / 255.0f)
#define INV_LOG256 (1.0f / 5.545177444479562f)   // 1/ln(256)

// mu-law (0..255) -> linear.  exp(u/128*ln256) == exp2(u/16)
__device__ __forceinline__ float u2l(float v) {
    float u = v - 128.0f;
    float a = fabsf(u);
    float m = SCALE_1 * (exp2f(a * 0.0625f) - 1.0f);
    return copysignf(m, u);
}

// linear -> mu-law (0..255), clipped
__device__ __forceinline__ float l2u(float x) {
    float a = fabsf(x);
    float u = 128.0f * log1pf(SCALE * a) * INV_LOG256;
    u = copysignf(u, x);
    return fminf(fmaxf(128.0f + u, 0.0f), 255.0f);
}

// One block per (batch, frame). 160 threads, each producing one output sample.
__global__ void diff_pred_kernel(const float* __restrict__ sig,
                                 const float* __restrict__ lpc,
                                 float* __restrict__ out) {
    __shared__ float sx[FRAME_SIZE + LPC_N];  // decoded samples incl. 16-halo
    __shared__ float sl[LPC_N];               // per-frame LPC coefficients

    const int frame = blockIdx.x;             // 0..14
    const int b     = blockIdx.y;             // 0..1023
    const int tid   = threadIdx.x;            // 0..159
    const int t0    = frame * FRAME_SIZE;

    const float* srow = sig + (size_t)b * T_LEN;

    // Halo: 16 samples before the frame start (zero-padded in LINEAR domain)
    if (tid < LPC_N) {
        int idx = t0 - LPC_N + tid;
        sx[tid] = (idx >= 0) ? u2l(srow[idx]) : 0.0f;
        sl[tid] = lpc[((size_t)b * N_FRAMES + frame) * LPC_N + tid];
    }
    // Main frame samples
    sx[LPC_N + tid] = u2l(srow[t0 + tid]);
    __syncthreads();

    // 16-tap FIR: pred[t] = -sum_i lpc[i] * xt[t - i]
    float acc = 0.0f;
#pragma unroll
    for (int i = 0; i < LPC_N; ++i) {
        acc = fmaf(sl[i], sx[LPC_N + tid - i], acc);
    }
    float pred = -acc;

    out[(size_t)b * T_LEN + t0 + tid] = l2u(pred);
}

extern "C" void kernel_launch(void* const* d_in, const int* in_sizes, int n_in,
                              void* d_out, int out_size) {
    const float* sig = (const float*)d_in[0];   // (B, T, 1) float32
    const float* lpc = (const float*)d_in[1];   // (B, 15, 16) float32
    float* out = (float*)d_out;                 // (B, T, 1) float32

    dim3 grid(N_FRAMES, B_SZ);
    dim3 block(FRAME_SIZE);
    diff_pred_kernel<<<grid, block>>>(sig, lpc, out);
}

// round 2
// speedup vs baseline: 1.5394x; 1.5394x over previous
#include <cuda_runtime.h>
#include <math.h>

#define FRAME_SIZE 160
#define LPC_N 16
#define T_LEN 2400          // 160 * 15
#define N_FRAMES 15
#define B_SZ 1024

#define FPB 3                         // frames per block
#define CHUNK (FRAME_SIZE * FPB)      // 480 samples
#define CHUNKS_PER_B (N_FRAMES / FPB) // 5
#define NTHREADS 128
#define NWORK (CHUNK / 4)             // 120 float4 work items

#define SCALE    (255.0f / 32768.0f)
#define SCALE_1  (32768.0f / 255.0f)

__device__ __forceinline__ float ex2_approx(float x) {
    float y; asm("ex2.approx.f32 %0, %1;" : "=f"(y) : "f"(x)); return y;
}
__device__ __forceinline__ float lg2_approx(float x) {
    float y; asm("lg2.approx.f32 %0, %1;" : "=f"(y) : "f"(x)); return y;
}

// mu-law (0..255) -> linear.  exp(u/128*ln256) == 2^(u/16)
__device__ __forceinline__ float u2l(float v) {
    float u = v - 128.0f;
    float a = fabsf(u);
    float m = SCALE_1 * (ex2_approx(a * 0.0625f) - 1.0f);
    return copysignf(m, u);
}

// linear -> mu-law: 128 + sign(x)*16*log2(1 + SCALE*|x|), clipped to [0,255]
__device__ __forceinline__ float l2u(float x) {
    float a = fabsf(x);
    float u = 16.0f * lg2_approx(fmaf(SCALE, a, 1.0f));
    u = copysignf(u, x);
    return fminf(fmaxf(128.0f + u, 0.0f), 255.0f);
}

// One block per (batch, 3-frame chunk). 128 threads; threads 0..119 each
// produce 4 consecutive output samples via float4 I/O.
__global__ __launch_bounds__(NTHREADS)
void diff_pred_kernel(const float4* __restrict__ sig,
                      const float*  __restrict__ lpc,
                      float4* __restrict__ out) {
    __shared__ float sx[LPC_N + CHUNK];   // 16-sample halo + 480 decoded samples
    __shared__ float sl[FPB * LPC_N];     // 3 frames x 16 coefficients
    float4* sx4 = (float4*)sx;

    const int bx  = blockIdx.x;
    const int b   = bx / CHUNKS_PER_B;
    const int ck  = bx % CHUNKS_PER_B;
    const int tid = threadIdx.x;

    const int row4 = b * (T_LEN / 4) + ck * (CHUNK / 4);  // float4 index of chunk start

    if (tid < NWORK) {
        // decode 4 samples of this chunk
        float4 v = sig[row4 + tid];
        float4 d;
        d.x = u2l(v.x); d.y = u2l(v.y); d.z = u2l(v.z); d.w = u2l(v.w);
        sx4[4 + tid] = d;
    } else if (tid < NWORK + 4) {
        // halo: 16 samples preceding the chunk (zeros at row start)
        int k = tid - NWORK;             // 0..3
        if (ck == 0) {
            sx4[k] = make_float4(0.f, 0.f, 0.f, 0.f);
        } else {
            float4 v = sig[row4 - 4 + k];
            float4 d;
            d.x = u2l(v.x); d.y = u2l(v.y); d.z = u2l(v.z); d.w = u2l(v.w);
            sx4[k] = d;
        }
    }
    if (tid < FPB * LPC_N) {
        sl[tid] = lpc[b * (N_FRAMES * LPC_N) + ck * (FPB * LPC_N) + tid];
    }
    __syncthreads();

    if (tid >= NWORK) return;

    // which frame (within this chunk) these 4 samples belong to
    const int f = tid / (FRAME_SIZE / 4);   // tid / 40, in 0..2

    // 16 per-frame coefficients (broadcast LDS.128)
    float c[LPC_N];
#pragma unroll
    for (int i = 0; i < LPC_N; i += 4) {
        float4 cc = *(const float4*)&sl[f * LPC_N + i];
        c[i] = cc.x; c[i + 1] = cc.y; c[i + 2] = cc.z; c[i + 3] = cc.w;
    }

    // 20-sample window sx[4*tid .. 4*tid+19] (5 aligned LDS.128)
    float x[20];
#pragma unroll
    for (int k = 0; k < 5; ++k) {
        float4 xx = sx4[tid + k];
        x[4 * k] = xx.x; x[4 * k + 1] = xx.y; x[4 * k + 2] = xx.z; x[4 * k + 3] = xx.w;
    }

    // output sample 4*tid + j uses x[16 + j - i], i = 0..15
    float a0 = 0.f, a1 = 0.f, a2 = 0.f, a3 = 0.f;
#pragma unroll
    for (int i = 0; i < LPC_N; ++i) {
        a0 = fmaf(c[i], x[16 - i], a0);
        a1 = fmaf(c[i], x[17 - i], a1);
        a2 = fmaf(c[i], x[18 - i], a2);
        a3 = fmaf(c[i], x[19 - i], a3);
    }

    float4 r;
    r.x = l2u(-a0); r.y = l2u(-a1); r.z = l2u(-a2); r.w = l2u(-a3);
    out[row4 + tid] = r;
}

extern "C" void kernel_launch(void* const* d_in, const int* in_sizes, int n_in,
                              void* d_out, int out_size) {
    const float4* sig = (const float4*)d_in[0];  // (B, 2400, 1) float32
    const float*  lpc = (const float*)d_in[1];   // (B, 15, 16) float32
    float4* out = (float4*)d_out;                // (B, 2400, 1) float32

    dim3 grid(B_SZ * CHUNKS_PER_B);              // 5120 blocks
    dim3 block(NTHREADS);
    diff_pred_kernel<<<grid, block>>>(sig, lpc, out);
}

// round 3
// speedup vs baseline: 1.5761x; 1.0239x over previous
#include <cuda_runtime.h>
#include <math.h>

#define FRAME_SIZE 160
#define LPC_N 16
#define T_LEN 2400
#define T4 (T_LEN / 4)        // 600
#define N_FRAMES 15
#define B_SZ 1024

#define FPB 3                          // frames per block
#define CHUNK (FRAME_SIZE * FPB)       // 480 samples (per row)
#define CHUNKS_PER_B (N_FRAMES / FPB)  // 5
#define NTHREADS 128
#define NWORK (CHUNK / 4)              // 120 work items (4 t-steps x 2 rows each)

#define SCALE    (255.0f / 32768.0f)
#define SCALE_1  (32768.0f / 255.0f)

typedef unsigned long long u64;

__device__ __forceinline__ float ex2_approx(float x) {
    float y; asm("ex2.approx.f32 %0, %1;" : "=f"(y) : "f"(x)); return y;
}
__device__ __forceinline__ float lg2_approx(float x) {
    float y; asm("lg2.approx.f32 %0, %1;" : "=f"(y) : "f"(x)); return y;
}
// packed fp32x2 fused multiply-add (FFMA2) — PTX-only on sm_103a
__device__ __forceinline__ u64 ffma2(u64 a, u64 b, u64 c) {
    u64 d; asm("fma.rn.f32x2 %0, %1, %2, %3;" : "=l"(d) : "l"(a), "l"(b), "l"(c));
    return d;
}
__device__ __forceinline__ float lo32(u64 v) { return __uint_as_float((unsigned)v); }
__device__ __forceinline__ float hi32(u64 v) { return __uint_as_float((unsigned)(v >> 32)); }

// mu-law (0..255) -> linear.  exp(u/128*ln256) == 2^(u/16)
__device__ __forceinline__ float u2l(float v) {
    float u = v - 128.0f;
    float m = fmaf(SCALE_1, ex2_approx(fabsf(u) * 0.0625f), -SCALE_1);
    return copysignf(m, u);
}
// l2u(-x): clip(128 - copysign(16*log2(1 + SCALE*|x|), x), 0, 255)
__device__ __forceinline__ float l2u_neg(float x) {
    float u = 16.0f * lg2_approx(fmaf(SCALE, fabsf(x), 1.0f));
    return fminf(fmaxf(128.0f - copysignf(u, x), 0.0f), 255.0f);
}

__device__ __forceinline__ float4 dec4(float4 v) {
    float4 d;
    d.x = u2l(v.x); d.y = u2l(v.y); d.z = u2l(v.z); d.w = u2l(v.w);
    return d;
}

// One block = 2 batch rows x 480-sample chunk. Decoded samples stored as
// interleaved float2 (lane0 = row b0, lane1 = row b0+1). FIR runs on packed
// fp32x2 FMAs: 8 FFMA2 per output sample instead of 16 scalar FFMA.
__global__ __launch_bounds__(NTHREADS)
void diff_pred_kernel(const float4* __restrict__ sig,
                      const float*  __restrict__ lpc,
                      float4* __restrict__ out) {
    __shared__ __align__(16) float2 sx2[LPC_N + CHUNK];  // halo + chunk, pairs
    __shared__ __align__(16) float2 sl2[FPB * LPC_N];    // coeff pairs

    const int bx  = blockIdx.x;
    const int p   = bx / CHUNKS_PER_B;     // row pair 0..511
    const int ck  = bx % CHUNKS_PER_B;     // chunk 0..4
    const int b0  = 2 * p;
    const int tid = threadIdx.x;
    const int base4 = ck * (CHUNK / 4);    // float4 offset of chunk in row

    if (tid < NWORK) {
        // decode 4 t-steps of both rows, store interleaved
        float4 d0 = dec4(sig[(size_t)b0 * T4 + base4 + tid]);
        float4 d1 = dec4(sig[(size_t)(b0 + 1) * T4 + base4 + tid]);
        float4* dst = (float4*)&sx2[LPC_N + 4 * tid];
        dst[0] = make_float4(d0.x, d1.x, d0.y, d1.y);
        dst[1] = make_float4(d0.z, d1.z, d0.w, d1.w);
    } else if (tid < NWORK + 4) {
        // halo: 16 samples preceding the chunk (zeros in linear domain at t<0)
        int k = tid - NWORK;               // 0..3
        float4* dst = (float4*)&sx2[4 * k];
        if (ck == 0) {
            dst[0] = make_float4(0.f, 0.f, 0.f, 0.f);
            dst[1] = make_float4(0.f, 0.f, 0.f, 0.f);
        } else {
            float4 d0 = dec4(sig[(size_t)b0 * T4 + base4 - 4 + k]);
            float4 d1 = dec4(sig[(size_t)(b0 + 1) * T4 + base4 - 4 + k]);
            dst[0] = make_float4(d0.x, d1.x, d0.y, d1.y);
            dst[1] = make_float4(d0.z, d1.z, d0.w, d1.w);
        }
    }
    if (tid < FPB * LPC_N) {
        int off = ck * (FPB * LPC_N) + tid;
        sl2[tid] = make_float2(lpc[(size_t)b0 * (N_FRAMES * LPC_N) + off],
                               lpc[(size_t)(b0 + 1) * (N_FRAMES * LPC_N) + off]);
    }
    __syncthreads();

    if (tid >= NWORK) return;

    const int f = tid / (FRAME_SIZE / 4);  // frame within chunk: 0..2
    const u64* cq = (const u64*)(sl2 + f * LPC_N);

    // 20-pair window sx2[4*tid .. 4*tid+19] as u64 lanes (10 LDS.128)
    u64 xw[20];
    const ulonglong2* sxq = (const ulonglong2*)(sx2 + 4 * tid);
#pragma unroll
    for (int k = 0; k < 10; ++k) {
        ulonglong2 t = sxq[k];
        xw[2 * k] = t.x; xw[2 * k + 1] = t.y;
    }

    // packed FIR: output pair j uses xw[16 + j - i]
    u64 a0 = 0ull, a1 = 0ull, a2 = 0ull, a3 = 0ull;
#pragma unroll
    for (int i = 0; i < LPC_N; ++i) {
        u64 c = cq[i];
        a0 = ffma2(c, xw[16 - i], a0);
        a1 = ffma2(c, xw[17 - i], a1);
        a2 = ffma2(c, xw[18 - i], a2);
        a3 = ffma2(c, xw[19 - i], a3);
    }

    float4 r0, r1;
    r0.x = l2u_neg(lo32(a0)); r1.x = l2u_neg(hi32(a0));
    r0.y = l2u_neg(lo32(a1)); r1.y = l2u_neg(hi32(a1));
    r0.z = l2u_neg(lo32(a2)); r1.z = l2u_neg(hi32(a2));
    r0.w = l2u_neg(lo32(a3)); r1.w = l2u_neg(hi32(a3));

    out[(size_t)b0 * T4 + base4 + tid] = r0;
    out[(size_t)(b0 + 1) * T4 + base4 + tid] = r1;
}

extern "C" void kernel_launch(void* const* d_in, const int* in_sizes, int n_in,
                              void* d_out, int out_size) {
    const float4* sig = (const float4*)d_in[0];  // (B, 2400, 1) f32
    const float*  lpc = (const float*)d_in[1];   // (B, 15, 16) f32
    float4* out = (float4*)d_out;                // (B, 2400, 1) f32

    dim3 grid((B_SZ / 2) * CHUNKS_PER_B);        // 2560 blocks
    dim3 block(NTHREADS);
    diff_pred_kernel<<<grid, block>>>(sig, lpc, out);
}